// round 6
// baseline (speedup 1.0000x reference)
#include <cuda_runtime.h>
#include <cuda_fp16.h>
#include <cstdint>

// ---------------------------------------------------------------------------
// JointNetwork: out[b,t,u,:] = tanh(a[bt,:] + t[bu,:]) @ W_j + b_j
//   a = audio[4,512,512] @ W_a[512,640] + b_a   -> [2048,640]
//   t = text [4,100,320] @ W_t[320,640] + b_t   -> [400,640]
//   big GEMM: M=204800, K=640, N=512, fp32 out
//
// NOTE: harness compiles at compute_103 (base) — tcgen05 is unavailable.
// Tensor path = mma.sync.m16n8k16 (HMMA) + ldmatrix + cp.async (sm_80 base).
// ---------------------------------------------------------------------------
#define HID   640
#define NCLS  512

// Scratch device globals (no allocation allowed)
__device__ __half g_a[2048 * HID];   // audio projection, fp16 (fp32-accurate GEMM)
__device__ __half g_t[400 * HID];    // text projection, fp16
__device__ __half g_wj[NCLS * HID];  // W_j^T as [v][h] (K-major B rows), fp16

// SMEM stage offsets (macros: device-visible, shift-friendly)
#define SA_STAGE(s) ((uint32_t)(s) * 16384u)
#define SB_STAGE(s) (32768u + (uint32_t)(s) * 32768u)
#define SMEM_BYTES  98304u

// ---------------------------------------------------------------------------
// helpers
// ---------------------------------------------------------------------------
__device__ __forceinline__ uint32_t smem_u32(const void* p) {
    uint32_t a;
    asm("{ .reg .u64 t; cvta.to.shared.u64 t, %1; cvt.u32.u64 %0, t; }" : "=r"(a) : "l"(p));
    return a;
}
__device__ __forceinline__ uint32_t swz128(uint32_t off) { return off ^ ((off >> 3) & 0x70); }

// accurate-enough tanh: 2 MUFU (ex2 + rcp); saturates correctly at +/-inf
__device__ __forceinline__ float tanh_fast(float x) {
    float e;
    asm("ex2.approx.f32 %0, %1;" : "=f"(e) : "f"(x * 2.8853900817779268f)); // e^{2x}
    float r;
    asm("rcp.approx.f32 %0, %1;" : "=f"(r) : "f"(e + 1.0f));
    return fmaf(-2.0f, r, 1.0f);
}

#define CP_ASYNC16(dst_u32, src_ptr) \
    asm volatile("cp.async.cg.shared.global [%0], [%1], 16;" \
        :: "r"(dst_u32), "l"(src_ptr) : "memory")
#define CP_ASYNC_COMMIT() asm volatile("cp.async.commit_group;" ::: "memory")
#define CP_ASYNC_WAIT0()  asm volatile("cp.async.wait_group 0;" ::: "memory")

#define LDSM_X4(r0, r1, r2, r3, addr) \
    asm volatile("ldmatrix.sync.aligned.m8n8.x4.shared.b16 {%0,%1,%2,%3}, [%4];" \
        : "=r"(r0), "=r"(r1), "=r"(r2), "=r"(r3) : "r"(addr))

#define MMA16816(d, a, b) \
    asm volatile("mma.sync.aligned.m16n8k16.row.col.f32.f16.f16.f32 " \
        "{%0,%1,%2,%3}, {%4,%5,%6,%7}, {%8,%9}, {%0,%1,%2,%3};" \
        : "+f"((d)[0]), "+f"((d)[1]), "+f"((d)[2]), "+f"((d)[3]) \
        : "r"((a)[0]), "r"((a)[1]), "r"((a)[2]), "r"((a)[3]), "r"((b)[0]), "r"((b)[1]))

// ---------------------------------------------------------------------------
// Projection SGEMM (fp32 compute, fp16 store): C[M,N] = A[M,K] @ W[K,N] + bias
// ---------------------------------------------------------------------------
__global__ __launch_bounds__(256) void sgemm_bias_kernel(
    const float* __restrict__ A, const float* __restrict__ W, const float* __restrict__ bias,
    int dst_sel, int M, int N, int K)
{
    __half* C = (dst_sel == 0) ? g_a : g_t;
    __shared__ float As[16][68];
    __shared__ float Bs[16][64];
    int tid = threadIdx.x;
    int bm = blockIdx.y * 64, bn = blockIdx.x * 64;
    int tx = tid & 15, ty = tid >> 4;
    int ar = tid >> 2, ak = (tid & 3) * 4;
    int bk = tid >> 4, bn4 = (tid & 15) * 4;
    float acc[4][4] = {};

    for (int k0 = 0; k0 < K; k0 += 16) {
        float4 av = make_float4(0.f, 0.f, 0.f, 0.f);
        if (bm + ar < M) av = *(const float4*)(A + (size_t)(bm + ar) * K + k0 + ak);
        As[ak + 0][ar] = av.x; As[ak + 1][ar] = av.y;
        As[ak + 2][ar] = av.z; As[ak + 3][ar] = av.w;
        *(float4*)&Bs[bk][bn4] = *(const float4*)(W + (size_t)(k0 + bk) * N + bn + bn4);
        __syncthreads();
#pragma unroll
        for (int k = 0; k < 16; k++) {
            float4 a4 = *(const float4*)&As[k][ty * 4];
            float4 b4 = *(const float4*)&Bs[k][tx * 4];
            float aa[4] = {a4.x, a4.y, a4.z, a4.w};
            float bb[4] = {b4.x, b4.y, b4.z, b4.w};
#pragma unroll
            for (int i = 0; i < 4; i++)
#pragma unroll
                for (int j = 0; j < 4; j++) acc[i][j] += aa[i] * bb[j];
        }
        __syncthreads();
    }
#pragma unroll
    for (int i = 0; i < 4; i++) {
        int m = bm + ty * 4 + i;
        if (m < M) {
#pragma unroll
            for (int j = 0; j < 4; j++) {
                int n = bn + tx * 4 + j;
                C[(size_t)m * N + n] = __float2half_rn(acc[i][j] + bias[n]);
            }
        }
    }
}

// ---------------------------------------------------------------------------
// W_j [640,512] fp32 -> g_wj [512][640] fp16 (transposed, K-major rows)
// ---------------------------------------------------------------------------
__global__ void convert_wj_kernel(const float* __restrict__ Wj) {
    int idx = blockIdx.x * 256 + threadIdx.x;   // 327680 total
    int v = idx / HID;
    int h = idx - v * HID;
    g_wj[idx] = __float2half_rn(Wj[h * NCLS + v]);
}

// ---------------------------------------------------------------------------
// Main fused HMMA kernel.
//   CTA: 512 threads (16 warps, 4x4), tile M=128, N=256. K=640 in 10 chunks of 64.
//   SMEM: A stages [0,16K),[16K,32K)  B stages [32K,64K),[64K,96K)
//   A tile produced in-SMEM: tanh(a+t) fp16, SW128 swizzle. B via cp.async.
// ---------------------------------------------------------------------------
static constexpr int THREADS = 512;
static constexpr int KCHUNKS = 10;

__global__ __launch_bounds__(THREADS, 1) void joint_main_kernel(
    const float* __restrict__ b_j, float* __restrict__ out)
{
    extern __shared__ __align__(1024) char smem[];
    const uint32_t sb = smem_u32(smem);
    const int tid  = threadIdx.x;
    const int lane = tid & 31;
    const int wid  = tid >> 5;
    const int warp_m = wid & 3;    // 0..3  (32-row slab)
    const int warp_n = wid >> 2;   // 0..3  (64-col slab)
    const int m0 = blockIdx.x * 128;
    const int n0 = blockIdx.y * 256;

    // --- producer-side row pointers (fixed per thread) ---
    const int pr = tid >> 2;          // row 0..127 of A tile
    const int pq = tid & 3;           // 16-half (32B) quarter of the 64-half chunk row
    const int m   = m0 + pr;
    const int bt  = m / 100;
    const int u   = m - bt * 100;
    const int trw = ((bt >> 9) * 100) + u;
    const __half* rowa = g_a + bt * HID + pq * 16;
    const __half* rowt = g_t + trw * HID + pq * 16;

    // --- B cp.async fixed mapping: 4 x 16B per thread ---
    const int b_row0   = tid >> 3;          // 0..63, +64 per i
    const int b_chunk  = tid & 7;           // 16B unit within 128B row
    const __half* wj_base = g_wj + (size_t)(n0 + b_row0) * HID + b_chunk * 8;

    float acc[2][8][4];
#pragma unroll
    for (int mt = 0; mt < 2; mt++)
#pragma unroll
        for (int nt = 0; nt < 8; nt++)
#pragma unroll
            for (int q = 0; q < 4; q++) acc[mt][nt][q] = 0.f;

    // ---- produce A chunk c into stage s ----
    auto produce = [&](int c, int s) {
        const __half* pa = rowa + c * 64;
        const __half* pt = rowt + c * 64;
#pragma unroll
        for (int j = 0; j < 2; j++) {
            uint4 av = *(const uint4*)(pa + j * 8);
            uint4 tv = *(const uint4*)(pt + j * 8);
            const __half2* ah = (const __half2*)&av;
            const __half2* th = (const __half2*)&tv;
            uint32_t rs[4];
#pragma unroll
            for (int q = 0; q < 4; q++) {
                float2 af = __half22float2(ah[q]);
                float2 tf = __half22float2(th[q]);
                __half2 h = __floats2half2_rn(tanh_fast(af.x + tf.x), tanh_fast(af.y + tf.y));
                rs[q] = *(uint32_t*)&h;
            }
            uint32_t off = (uint32_t)(pr * 128 + pq * 32 + j * 16);
            *(uint4*)(smem + SA_STAGE(s) + swz128(off)) = make_uint4(rs[0], rs[1], rs[2], rs[3]);
        }
    };

    // ---- cp.async B chunk c into stage s ----
    auto loadB = [&](int c, int s) {
        const __half* src = wj_base + c * 64;
#pragma unroll
        for (int i = 0; i < 4; i++) {
            uint32_t off = (uint32_t)((b_row0 + i * 64) * 128 + b_chunk * 16);
            CP_ASYNC16(sb + SB_STAGE(s) + swz128(off), src + (size_t)i * 64 * HID);
        }
        CP_ASYNC_COMMIT();
    };

    // ---- prologue ----
    produce(0, 0);
    loadB(0, 0);

    // ---- main loop ----
    for (int c = 0; c < KCHUNKS; c++) {
        const int s = c & 1;
        CP_ASYNC_WAIT0();
        __syncthreads();                       // stage s ready; stage s^1 free

        if (c + 1 < KCHUNKS) loadB(c + 1, s ^ 1);

        const uint32_t aBase = sb + SA_STAGE(s);
        const uint32_t bBase = sb + SB_STAGE(s);

#pragma unroll
        for (int ks = 0; ks < 4; ks++) {
            uint32_t afr[2][4];
#pragma unroll
            for (int mt = 0; mt < 2; mt++) {
                int row = warp_m * 32 + mt * 16 + (lane & 15);
                uint32_t off = (uint32_t)(row * 128 + ks * 32 + (lane >> 4) * 16);
                LDSM_X4(afr[mt][0], afr[mt][1], afr[mt][2], afr[mt][3], aBase + swz128(off));
            }
            uint32_t bfr[8][2];
#pragma unroll
            for (int p = 0; p < 4; p++) {
                int tl = lane >> 3, rr = lane & 7;
                int row = warp_n * 64 + p * 16 + (tl >> 1) * 8 + rr;
                uint32_t off = (uint32_t)(row * 128 + ks * 32 + (tl & 1) * 16);
                uint32_t r0, r1, r2, r3;
                LDSM_X4(r0, r1, r2, r3, bBase + swz128(off));
                bfr[p * 2 + 0][0] = r0; bfr[p * 2 + 0][1] = r1;
                bfr[p * 2 + 1][0] = r2; bfr[p * 2 + 1][1] = r3;
            }
#pragma unroll
            for (int mt = 0; mt < 2; mt++)
#pragma unroll
                for (int nt = 0; nt < 8; nt++)
                    MMA16816(acc[mt][nt], afr[mt], bfr[nt]);
        }

        if (c + 1 < KCHUNKS) produce(c + 1, s ^ 1);
    }

    // ---- epilogue: + bias, fp32 stores ----
    const int r0 = m0 + warp_m * 32 + (lane >> 2);
    float* outp = out + (size_t)r0 * NCLS;
#pragma unroll
    for (int nt = 0; nt < 8; nt++) {
        int col = n0 + warp_n * 64 + nt * 8 + (lane & 3) * 2;
        float bj0 = b_j[col], bj1 = b_j[col + 1];
#pragma unroll
        for (int mt = 0; mt < 2; mt++) {
            float* p = outp + (size_t)mt * 16 * NCLS + col;
            *(float2*)p              = make_float2(acc[mt][nt][0] + bj0, acc[mt][nt][1] + bj1);
            *(float2*)(p + 8 * NCLS) = make_float2(acc[mt][nt][2] + bj0, acc[mt][nt][3] + bj1);
        }
    }
}

// ---------------------------------------------------------------------------
extern "C" void kernel_launch(void* const* d_in, const int* in_sizes, int n_in,
                              void* d_out, int out_size) {
    const float* audio = (const float*)d_in[0];
    const float* text  = (const float*)d_in[1];
    const float* W_a   = (const float*)d_in[2];
    const float* b_a   = (const float*)d_in[3];
    const float* W_t   = (const float*)d_in[4];
    const float* b_t   = (const float*)d_in[5];
    const float* W_j   = (const float*)d_in[6];
    const float* b_j   = (const float*)d_in[7];
    float* out = (float*)d_out;

    sgemm_bias_kernel<<<dim3(10, 32), 256>>>(audio, W_a, b_a, 0, 2048, HID, 512);
    sgemm_bias_kernel<<<dim3(10, 7),  256>>>(text,  W_t, b_t, 1, 400,  HID, 320);
    convert_wj_kernel<<<1280, 256>>>(W_j);

    cudaFuncSetAttribute(joint_main_kernel, cudaFuncAttributeMaxDynamicSharedMemorySize,
                         SMEM_BYTES);
    joint_main_kernel<<<dim3(1600, 2), THREADS, SMEM_BYTES>>>(b_j, out);
}

// round 7
// speedup vs baseline: 1.0305x; 1.0305x over previous
#include <cuda_runtime.h>
#include <cuda_fp16.h>
#include <cstdint>

// ---------------------------------------------------------------------------
// JointNetwork: out[b,t,u,:] = tanh(a[bt,:] + t[bu,:]) @ W_j + b_j
//   big GEMM: M=204800, K=640, N=512, fp32 out
// Tensor path = mma.sync.m16n8k16 (HMMA) + ldmatrix + cp.async (compute_103 base).
// R6: tanh producer interleaved into MMA loop; prep kernels fused.
// ---------------------------------------------------------------------------
#define HID   640
#define NCLS  512

__device__ __half g_a[2048 * HID];   // audio projection, fp16 (fp32-accurate GEMM)
__device__ __half g_t[400 * HID];    // text projection, fp16
__device__ __half g_wj[NCLS * HID];  // W_j^T as [v][h] (K-major B rows), fp16

#define SA_STAGE(s) ((uint32_t)(s) * 16384u)
#define SB_STAGE(s) (32768u + (uint32_t)(s) * 32768u)
#define SMEM_BYTES  98304u

// ---------------------------------------------------------------------------
__device__ __forceinline__ uint32_t smem_u32(const void* p) {
    uint32_t a;
    asm("{ .reg .u64 t; cvta.to.shared.u64 t, %1; cvt.u32.u64 %0, t; }" : "=r"(a) : "l"(p));
    return a;
}
__device__ __forceinline__ uint32_t swz128(uint32_t off) { return off ^ ((off >> 3) & 0x70); }

__device__ __forceinline__ float tanh_fast(float x) {
    float e;
    asm("ex2.approx.f32 %0, %1;" : "=f"(e) : "f"(x * 2.8853900817779268f)); // e^{2x}
    float r;
    asm("rcp.approx.f32 %0, %1;" : "=f"(r) : "f"(e + 1.0f));
    return fmaf(-2.0f, r, 1.0f);
}

#define CP_ASYNC16(dst_u32, src_ptr) \
    asm volatile("cp.async.cg.shared.global [%0], [%1], 16;" \
        :: "r"(dst_u32), "l"(src_ptr) : "memory")
#define CP_ASYNC_COMMIT() asm volatile("cp.async.commit_group;" ::: "memory")
#define CP_ASYNC_WAIT0()  asm volatile("cp.async.wait_group 0;" ::: "memory")

#define LDSM_X4(r0, r1, r2, r3, addr) \
    asm volatile("ldmatrix.sync.aligned.m8n8.x4.shared.b16 {%0,%1,%2,%3}, [%4];" \
        : "=r"(r0), "=r"(r1), "=r"(r2), "=r"(r3) : "r"(addr))

#define MMA16816(d, a, b) \
    asm volatile("mma.sync.aligned.m16n8k16.row.col.f32.f16.f16.f32 " \
        "{%0,%1,%2,%3}, {%4,%5,%6,%7}, {%8,%9}, {%0,%1,%2,%3};" \
        : "+f"((d)[0]), "+f"((d)[1]), "+f"((d)[2]), "+f"((d)[3]) \
        : "r"((a)[0]), "r"((a)[1]), "r"((a)[2]), "r"((a)[3]), "r"((b)[0]), "r"((b)[1]))

// ---------------------------------------------------------------------------
// Fused prep: blocks [0,320) audio proj, [320,390) text proj, [390,1670) Wj cvt
// ---------------------------------------------------------------------------
__device__ void sgemm_body(const float* __restrict__ A, const float* __restrict__ W,
                           const float* __restrict__ bias, __half* __restrict__ C,
                           int M, int K, int bx, int by)
{
    __shared__ float As[16][68];
    __shared__ float Bs[16][64];
    const int N = HID;
    int tid = threadIdx.x;
    int bm = by * 64, bn = bx * 64;
    int tx = tid & 15, ty = tid >> 4;
    int ar = tid >> 2, ak = (tid & 3) * 4;
    int bk = tid >> 4, bn4 = (tid & 15) * 4;
    float acc[4][4] = {};

    for (int k0 = 0; k0 < K; k0 += 16) {
        float4 av = make_float4(0.f, 0.f, 0.f, 0.f);
        if (bm + ar < M) av = *(const float4*)(A + (size_t)(bm + ar) * K + k0 + ak);
        As[ak + 0][ar] = av.x; As[ak + 1][ar] = av.y;
        As[ak + 2][ar] = av.z; As[ak + 3][ar] = av.w;
        *(float4*)&Bs[bk][bn4] = *(const float4*)(W + (size_t)(k0 + bk) * N + bn + bn4);
        __syncthreads();
#pragma unroll
        for (int k = 0; k < 16; k++) {
            float4 a4 = *(const float4*)&As[k][ty * 4];
            float4 b4 = *(const float4*)&Bs[k][tx * 4];
            float aa[4] = {a4.x, a4.y, a4.z, a4.w};
            float bb[4] = {b4.x, b4.y, b4.z, b4.w};
#pragma unroll
            for (int i = 0; i < 4; i++)
#pragma unroll
                for (int j = 0; j < 4; j++) acc[i][j] += aa[i] * bb[j];
        }
        __syncthreads();
    }
#pragma unroll
    for (int i = 0; i < 4; i++) {
        int m = bm + ty * 4 + i;
        if (m < M) {
#pragma unroll
            for (int j = 0; j < 4; j++) {
                int n = bn + tx * 4 + j;
                C[(size_t)m * N + n] = __float2half_rn(acc[i][j] + bias[n]);
            }
        }
    }
}

__global__ __launch_bounds__(256) void prep_kernel(
    const float* __restrict__ audio, const float* __restrict__ text,
    const float* __restrict__ W_a, const float* __restrict__ b_a,
    const float* __restrict__ W_t, const float* __restrict__ b_t,
    const float* __restrict__ W_j)
{
    int blk = blockIdx.x;
    if (blk < 320) {
        sgemm_body(audio, W_a, b_a, g_a, 2048, 512, blk % 10, blk / 10);
    } else if (blk < 390) {
        int b = blk - 320;
        sgemm_body(text, W_t, b_t, g_t, 400, 320, b % 10, b / 10);
    } else {
        int idx = (blk - 390) * 256 + threadIdx.x;   // [0, 327680)
        int v = idx / HID;
        int h = idx - v * HID;
        g_wj[idx] = __float2half_rn(W_j[h * NCLS + v]);
    }
}

// ---------------------------------------------------------------------------
// Main fused HMMA kernel: 512 thr (16 warps 4x4), tile M128 x N256, K in 10x64.
// tanh producer interleaved into the ks-loop (MUFU under HMMA shadow).
// ---------------------------------------------------------------------------
static constexpr int THREADS = 512;
static constexpr int KCHUNKS = 10;

__global__ __launch_bounds__(THREADS, 1) void joint_main_kernel(
    const float* __restrict__ b_j, float* __restrict__ out)
{
    extern __shared__ __align__(1024) char smem[];
    const uint32_t sb = smem_u32(smem);
    const int tid  = threadIdx.x;
    const int lane = tid & 31;
    const int wid  = tid >> 5;
    const int warp_m = wid & 3;
    const int warp_n = wid >> 2;
    const int m0 = blockIdx.x * 128;
    const int n0 = blockIdx.y * 256;

    // producer mapping: thread -> (row pr, 16-half quarter pq)
    const int pr = tid >> 2;
    const int pq = tid & 3;
    const int m   = m0 + pr;
    const int bt  = m / 100;
    const int u   = m - bt * 100;
    const int trw = ((bt >> 9) * 100) + u;
    const __half* rowa = g_a + bt * HID + pq * 16;
    const __half* rowt = g_t + trw * HID + pq * 16;
    const uint32_t aoff = (uint32_t)(pr * 128 + pq * 32);

    // B cp.async mapping: 4 x 16B per thread
    const int b_row0  = tid >> 3;
    const int b_chunk = tid & 7;
    const __half* wj_base = g_wj + (size_t)(n0 + b_row0) * HID + b_chunk * 8;

    float acc[2][8][4];
#pragma unroll
    for (int mt = 0; mt < 2; mt++)
#pragma unroll
        for (int nt = 0; nt < 8; nt++)
#pragma unroll
            for (int q = 0; q < 4; q++) acc[mt][nt][q] = 0.f;

    auto loadB = [&](int c, int s) {
        const __half* src = wj_base + c * 64;
#pragma unroll
        for (int i = 0; i < 4; i++) {
            uint32_t off = (uint32_t)((b_row0 + i * 64) * 128 + b_chunk * 16);
            CP_ASYNC16(sb + SB_STAGE(s) + swz128(off), src + (size_t)i * 64 * HID);
        }
        CP_ASYNC_COMMIT();
    };

    // tanh one 16B quarter (j in {0,1}) from prefetched regs into stage s
    auto tanh_quarter = [&](uint4 av, uint4 tv, int j, int s) {
        const __half2* ah = (const __half2*)&av;
        const __half2* th = (const __half2*)&tv;
        uint32_t rs[4];
#pragma unroll
        for (int q = 0; q < 4; q++) {
            float2 af = __half22float2(ah[q]);
            float2 tf = __half22float2(th[q]);
            __half2 h = __floats2half2_rn(tanh_fast(af.x + tf.x), tanh_fast(af.y + tf.y));
            rs[q] = *(uint32_t*)&h;
        }
        *(uint4*)(smem + SA_STAGE(s) + swz128(aoff + (uint32_t)j * 16)) =
            make_uint4(rs[0], rs[1], rs[2], rs[3]);
    };

    // ---- prologue: produce chunk 0, start B chunk 0 ----
    {
        uint4 av0 = *(const uint4*)(rowa);
        uint4 tv0 = *(const uint4*)(rowt);
        uint4 av1 = *(const uint4*)(rowa + 8);
        uint4 tv1 = *(const uint4*)(rowt + 8);
        tanh_quarter(av0, tv0, 0, 0);
        tanh_quarter(av1, tv1, 1, 0);
    }
    loadB(0, 0);

    // ---- main loop ----
    for (int c = 0; c < KCHUNKS; c++) {
        const int s = c & 1;
        CP_ASYNC_WAIT0();
        __syncthreads();                 // stage s ready; stage s^1 free

        const bool more = (c + 1 < KCHUNKS);
        if (more) loadB(c + 1, s ^ 1);

        const __half* pa = rowa + (c + 1) * 64;
        const __half* pt = rowt + (c + 1) * 64;
        uint4 av0, tv0, av1, tv1;
        if (more) { av0 = *(const uint4*)pa; tv0 = *(const uint4*)pt; }

        const uint32_t aBase = sb + SA_STAGE(s);
        const uint32_t bBase = sb + SB_STAGE(s);

#pragma unroll
        for (int ks = 0; ks < 4; ks++) {
            uint32_t afr[2][4];
#pragma unroll
            for (int mt = 0; mt < 2; mt++) {
                int row = warp_m * 32 + mt * 16 + (lane & 15);
                uint32_t off = (uint32_t)(row * 128 + ks * 32 + (lane >> 4) * 16);
                LDSM_X4(afr[mt][0], afr[mt][1], afr[mt][2], afr[mt][3], aBase + swz128(off));
            }
            uint32_t bfr[8][2];
#pragma unroll
            for (int p = 0; p < 4; p++) {
                int tl = lane >> 3, rr = lane & 7;
                int row = warp_n * 64 + p * 16 + (tl >> 1) * 8 + rr;
                uint32_t off = (uint32_t)(row * 128 + ks * 32 + (tl & 1) * 16);
                uint32_t r0, r1, r2, r3;
                LDSM_X4(r0, r1, r2, r3, bBase + swz128(off));
                bfr[p * 2 + 0][0] = r0; bfr[p * 2 + 0][1] = r1;
                bfr[p * 2 + 1][0] = r2; bfr[p * 2 + 1][1] = r3;
            }

            if (ks == 1 && more) { av1 = *(const uint4*)(pa + 8); tv1 = *(const uint4*)(pt + 8); }

#pragma unroll
            for (int mt = 0; mt < 2; mt++)
#pragma unroll
                for (int nt = 0; nt < 8; nt++)
                    MMA16816(acc[mt][nt], afr[mt], bfr[nt]);

            // interleave tanh producer under the HMMA shadow
            if (ks == 0 && more) tanh_quarter(av0, tv0, 0, s ^ 1);
            if (ks == 2 && more) tanh_quarter(av1, tv1, 1, s ^ 1);
        }
    }

    // ---- epilogue: + bias, fp32 stores ----
    const int r0 = m0 + warp_m * 32 + (lane >> 2);
    float* outp = out + (size_t)r0 * NCLS;
#pragma unroll
    for (int nt = 0; nt < 8; nt++) {
        int col = n0 + warp_n * 64 + nt * 8 + (lane & 3) * 2;
        float bj0 = b_j[col], bj1 = b_j[col + 1];
#pragma unroll
        for (int mt = 0; mt < 2; mt++) {
            float* p = outp + (size_t)mt * 16 * NCLS + col;
            *(float2*)p              = make_float2(acc[mt][nt][0] + bj0, acc[mt][nt][1] + bj1);
            *(float2*)(p + 8 * NCLS) = make_float2(acc[mt][nt][2] + bj0, acc[mt][nt][3] + bj1);
        }
    }
}

// ---------------------------------------------------------------------------
extern "C" void kernel_launch(void* const* d_in, const int* in_sizes, int n_in,
                              void* d_out, int out_size) {
    const float* audio = (const float*)d_in[0];
    const float* text  = (const float*)d_in[1];
    const float* W_a   = (const float*)d_in[2];
    const float* b_a   = (const float*)d_in[3];
    const float* W_t   = (const float*)d_in[4];
    const float* b_t   = (const float*)d_in[5];
    const float* W_j   = (const float*)d_in[6];
    const float* b_j   = (const float*)d_in[7];
    float* out = (float*)d_out;

    prep_kernel<<<1670, 256>>>(audio, text, W_a, b_a, W_t, b_t, W_j);

    cudaFuncSetAttribute(joint_main_kernel, cudaFuncAttributeMaxDynamicSharedMemorySize,
                         SMEM_BYTES);
    joint_main_kernel<<<dim3(1600, 2), THREADS, SMEM_BYTES>>>(b_j, out);
}

// round 9
// speedup vs baseline: 1.0767x; 1.0448x over previous
#include <cuda_runtime.h>
#include <cuda_fp16.h>
#include <cstdint>

// ---------------------------------------------------------------------------
// JointNetwork: out[b,t,u,:] = tanh(a[bt,:] + t[bu,:]) @ W_j + b_j
//   big GEMM: M=204800, K=640, N=512, fp32 out
// R8: fix R7 producer coverage bug (each thread now writes its full 32-B
//     quarter: two uint4 stores). Tile M64xN256, 256 thr, 2 CTAs/SM.
// ---------------------------------------------------------------------------
#define HID   640
#define NCLS  512

__device__ __half g_a[2048 * HID];   // audio projection, fp16
__device__ __half g_t[400 * HID];    // text projection, fp16
__device__ __half g_wj[NCLS * HID];  // W_j^T as [v][h] (K-major B rows), fp16

// SMEM: A stages 8KB @ {0, 8K}; B stages 32KB @ {16K, 48K}; total 80KB
#define SA_STAGE(s) ((uint32_t)(s) * 8192u)
#define SB_STAGE(s) (16384u + (uint32_t)(s) * 32768u)
#define SMEM_BYTES  81920u

// ---------------------------------------------------------------------------
__device__ __forceinline__ uint32_t smem_u32(const void* p) {
    uint32_t a;
    asm("{ .reg .u64 t; cvta.to.shared.u64 t, %1; cvt.u32.u64 %0, t; }" : "=r"(a) : "l"(p));
    return a;
}
__device__ __forceinline__ uint32_t swz128(uint32_t off) { return off ^ ((off >> 3) & 0x70); }

__device__ __forceinline__ float tanh_fast(float x) {
    float e;
    asm("ex2.approx.f32 %0, %1;" : "=f"(e) : "f"(x * 2.8853900817779268f)); // e^{2x}
    float r;
    asm("rcp.approx.f32 %0, %1;" : "=f"(r) : "f"(e + 1.0f));
    return fmaf(-2.0f, r, 1.0f);
}

#define CP_ASYNC16(dst_u32, src_ptr) \
    asm volatile("cp.async.cg.shared.global [%0], [%1], 16;" \
        :: "r"(dst_u32), "l"(src_ptr) : "memory")
#define CP_ASYNC_COMMIT() asm volatile("cp.async.commit_group;" ::: "memory")
#define CP_ASYNC_WAIT0()  asm volatile("cp.async.wait_group 0;" ::: "memory")

#define LDSM_X4(r0, r1, r2, r3, addr) \
    asm volatile("ldmatrix.sync.aligned.m8n8.x4.shared.b16 {%0,%1,%2,%3}, [%4];" \
        : "=r"(r0), "=r"(r1), "=r"(r2), "=r"(r3) : "r"(addr))

#define MMA16816(d, a, b) \
    asm volatile("mma.sync.aligned.m16n8k16.row.col.f32.f16.f16.f32 " \
        "{%0,%1,%2,%3}, {%4,%5,%6,%7}, {%8,%9}, {%0,%1,%2,%3};" \
        : "+f"((d)[0]), "+f"((d)[1]), "+f"((d)[2]), "+f"((d)[3]) \
        : "r"((a)[0]), "r"((a)[1]), "r"((a)[2]), "r"((a)[3]), "r"((b)[0]), "r"((b)[1]))

// ---------------------------------------------------------------------------
// Fused prep: blocks [0,320) audio proj, [320,390) text proj, [390,1670) Wj cvt
// ---------------------------------------------------------------------------
__device__ void sgemm_body(const float* __restrict__ A, const float* __restrict__ W,
                           const float* __restrict__ bias, __half* __restrict__ C,
                           int M, int K, int bx, int by)
{
    __shared__ float As[16][68];
    __shared__ float Bs[16][64];
    const int N = HID;
    int tid = threadIdx.x;
    int bm = by * 64, bn = bx * 64;
    int tx = tid & 15, ty = tid >> 4;
    int ar = tid >> 2, ak = (tid & 3) * 4;
    int bk = tid >> 4, bn4 = (tid & 15) * 4;
    float acc[4][4] = {};

    for (int k0 = 0; k0 < K; k0 += 16) {
        float4 av = make_float4(0.f, 0.f, 0.f, 0.f);
        if (bm + ar < M) av = *(const float4*)(A + (size_t)(bm + ar) * K + k0 + ak);
        As[ak + 0][ar] = av.x; As[ak + 1][ar] = av.y;
        As[ak + 2][ar] = av.z; As[ak + 3][ar] = av.w;
        *(float4*)&Bs[bk][bn4] = *(const float4*)(W + (size_t)(k0 + bk) * N + bn + bn4);
        __syncthreads();
#pragma unroll
        for (int k = 0; k < 16; k++) {
            float4 a4 = *(const float4*)&As[k][ty * 4];
            float4 b4 = *(const float4*)&Bs[k][tx * 4];
            float aa[4] = {a4.x, a4.y, a4.z, a4.w};
            float bb[4] = {b4.x, b4.y, b4.z, b4.w};
#pragma unroll
            for (int i = 0; i < 4; i++)
#pragma unroll
                for (int j = 0; j < 4; j++) acc[i][j] += aa[i] * bb[j];
        }
        __syncthreads();
    }
#pragma unroll
    for (int i = 0; i < 4; i++) {
        int m = bm + ty * 4 + i;
        if (m < M) {
#pragma unroll
            for (int j = 0; j < 4; j++) {
                int n = bn + tx * 4 + j;
                C[(size_t)m * N + n] = __float2half_rn(acc[i][j] + bias[n]);
            }
        }
    }
}

__global__ __launch_bounds__(256) void prep_kernel(
    const float* __restrict__ audio, const float* __restrict__ text,
    const float* __restrict__ W_a, const float* __restrict__ b_a,
    const float* __restrict__ W_t, const float* __restrict__ b_t,
    const float* __restrict__ W_j)
{
    int blk = blockIdx.x;
    if (blk < 320) {
        sgemm_body(audio, W_a, b_a, g_a, 2048, 512, blk % 10, blk / 10);
    } else if (blk < 390) {
        int b = blk - 320;
        sgemm_body(text, W_t, b_t, g_t, 400, 320, b % 10, b / 10);
    } else {
        int idx = (blk - 390) * 256 + threadIdx.x;   // [0, 327680)
        int v = idx / HID;
        int h = idx - v * HID;
        g_wj[idx] = __float2half_rn(W_j[h * NCLS + v]);
    }
}

// ---------------------------------------------------------------------------
// Main HMMA kernel: 256 thr (8 warps, 2x4), tile M64 x N256, K in 10x64.
// ---------------------------------------------------------------------------
static constexpr int THREADS = 256;
static constexpr int KCHUNKS = 10;

__global__ __launch_bounds__(THREADS, 2) void joint_main_kernel(
    const float* __restrict__ b_j, float* __restrict__ out)
{
    extern __shared__ __align__(1024) char smem[];
    const uint32_t sb = smem_u32(smem);
    const int tid  = threadIdx.x;
    const int lane = tid & 31;
    const int wid  = tid >> 5;
    const int warp_m = wid & 1;    // 0..1 (32-row slab)
    const int warp_n = wid >> 1;   // 0..3 (64-col slab)
    const int m0 = blockIdx.x * 64;
    const int n0 = blockIdx.y * 256;

    // producer mapping: one 32-B quarter (16 halves) per thread per chunk
    const int pr = tid >> 2;          // row 0..63
    const int pq = tid & 3;           // quarter 0..3
    const int m   = m0 + pr;
    const int bt  = m / 100;
    const int u   = m - bt * 100;
    const int trw = ((bt >> 9) * 100) + u;
    const __half* rowa = g_a + bt * HID + pq * 16;
    const __half* rowt = g_t + trw * HID + pq * 16;
    const uint32_t abase_off = (uint32_t)(pr * 128 + pq * 32);  // un-swizzled

    // B cp.async mapping: 8 x 16B per thread per chunk (256 rows x 8 chunks)
    const int b_row0  = tid >> 3;     // 0..31, +32 per i
    const int b_chunk = tid & 7;
    const __half* wj_base = g_wj + (size_t)(n0 + b_row0) * HID + b_chunk * 8;

    float acc[2][8][4];
#pragma unroll
    for (int mt = 0; mt < 2; mt++)
#pragma unroll
        for (int nt = 0; nt < 8; nt++)
#pragma unroll
            for (int q = 0; q < 4; q++) acc[mt][nt][q] = 0.f;

    auto loadB = [&](int c, int s) {
        const __half* src = wj_base + c * 64;
#pragma unroll
        for (int i = 0; i < 8; i++) {
            uint32_t off = (uint32_t)((b_row0 + i * 32) * 128 + b_chunk * 16);
            CP_ASYNC16(sb + SB_STAGE(s) + swz128(off), src + (size_t)i * 32 * HID);
        }
        CP_ASYNC_COMMIT();
    };

    // full 32-B quarter: two 16-B halves (j = 0,1), swizzle applied per store
    auto tanh_half = [&](uint4 av, uint4 tv, int j, int s) {
        const __half2* ah = (const __half2*)&av;
        const __half2* th = (const __half2*)&tv;
        uint32_t rs[4];
#pragma unroll
        for (int q = 0; q < 4; q++) {
            float2 af = __half22float2(ah[q]);
            float2 tf = __half22float2(th[q]);
            __half2 h = __floats2half2_rn(tanh_fast(af.x + tf.x), tanh_fast(af.y + tf.y));
            rs[q] = *(uint32_t*)&h;
        }
        *(uint4*)(smem + SA_STAGE(s) + swz128(abase_off + (uint32_t)j * 16)) =
            make_uint4(rs[0], rs[1], rs[2], rs[3]);
    };

    // ---- prologue: produce full chunk 0, start B chunk 0 ----
    {
        uint4 av0 = *(const uint4*)rowa;
        uint4 tv0 = *(const uint4*)rowt;
        uint4 av1 = *(const uint4*)(rowa + 8);
        uint4 tv1 = *(const uint4*)(rowt + 8);
        tanh_half(av0, tv0, 0, 0);
        tanh_half(av1, tv1, 1, 0);
    }
    loadB(0, 0);

    // ---- main loop ----
    for (int c = 0; c < KCHUNKS; c++) {
        const int s = c & 1;
        CP_ASYNC_WAIT0();
        __syncthreads();                 // stage s ready; stage s^1 free

        const bool more = (c + 1 < KCHUNKS);
        if (more) loadB(c + 1, s ^ 1);

        const __half* pa = rowa + (c + 1) * 64;
        const __half* pt = rowt + (c + 1) * 64;
        uint4 av0, tv0, av1, tv1;
        if (more) { av0 = *(const uint4*)pa; tv0 = *(const uint4*)pt; }

        const uint32_t aBase = sb + SA_STAGE(s);
        const uint32_t bBase = sb + SB_STAGE(s);

#pragma unroll
        for (int ks = 0; ks < 4; ks++) {
            uint32_t afr[2][4];
#pragma unroll
            for (int mt = 0; mt < 2; mt++) {
                int row = warp_m * 32 + mt * 16 + (lane & 15);
                uint32_t off = (uint32_t)(row * 128 + ks * 32 + (lane >> 4) * 16);
                LDSM_X4(afr[mt][0], afr[mt][1], afr[mt][2], afr[mt][3], aBase + swz128(off));
            }
            uint32_t bfr[8][2];
#pragma unroll
            for (int p = 0; p < 4; p++) {
                int tl = lane >> 3, rr = lane & 7;
                int row = warp_n * 64 + p * 16 + (tl >> 1) * 8 + rr;
                uint32_t off = (uint32_t)(row * 128 + ks * 32 + (tl & 1) * 16);
                uint32_t r0, r1, r2, r3;
                LDSM_X4(r0, r1, r2, r3, bBase + swz128(off));
                bfr[p * 2 + 0][0] = r0; bfr[p * 2 + 0][1] = r1;
                bfr[p * 2 + 1][0] = r2; bfr[p * 2 + 1][1] = r3;
            }

            if (ks == 1 && more) { av1 = *(const uint4*)(pa + 8); tv1 = *(const uint4*)(pt + 8); }

#pragma unroll
            for (int mt = 0; mt < 2; mt++)
#pragma unroll
                for (int nt = 0; nt < 8; nt++)
                    MMA16816(acc[mt][nt], afr[mt], bfr[nt]);

            if (ks == 0 && more) tanh_half(av0, tv0, 0, s ^ 1);
            if (ks == 2 && more) tanh_half(av1, tv1, 1, s ^ 1);
        }
    }

    // ---- epilogue: + bias, fp32 stores ----
    const int r0 = m0 + warp_m * 32 + (lane >> 2);
    float* outp = out + (size_t)r0 * NCLS;
#pragma unroll
    for (int nt = 0; nt < 8; nt++) {
        int col = n0 + warp_n * 64 + nt * 8 + (lane & 3) * 2;
        float bj0 = b_j[col], bj1 = b_j[col + 1];
#pragma unroll
        for (int mt = 0; mt < 2; mt++) {
            float* p = outp + (size_t)mt * 16 * NCLS + col;
            *(float2*)p              = make_float2(acc[mt][nt][0] + bj0, acc[mt][nt][1] + bj1);
            *(float2*)(p + 8 * NCLS) = make_float2(acc[mt][nt][2] + bj0, acc[mt][nt][3] + bj1);
        }
    }
}

// ---------------------------------------------------------------------------
extern "C" void kernel_launch(void* const* d_in, const int* in_sizes, int n_in,
                              void* d_out, int out_size) {
    const float* audio = (const float*)d_in[0];
    const float* text  = (const float*)d_in[1];
    const float* W_a   = (const float*)d_in[2];
    const float* b_a   = (const float*)d_in[3];
    const float* W_t   = (const float*)d_in[4];
    const float* b_t   = (const float*)d_in[5];
    const float* W_j   = (const float*)d_in[6];
    const float* b_j   = (const float*)d_in[7];
    float* out = (float*)d_out;

    prep_kernel<<<1670, 256>>>(audio, text, W_a, b_a, W_t, b_t, W_j);

    cudaFuncSetAttribute(joint_main_kernel, cudaFuncAttributeMaxDynamicSharedMemorySize,
                         SMEM_BYTES);
    joint_main_kernel<<<dim3(3200, 2), THREADS, SMEM_BYTES>>>(b_j, out);
}